// round 11
// baseline (speedup 1.0000x reference)
#include <cuda_runtime.h>
#include <cuda_fp16.h>

// CostVolumeManager: plane-sweep cost volume. B=1, S=8, C=16, H=64, W=96, D=64.
//
// v7: explicit 2-stage software pipeline across sources.
//   Diagnosis: all prior variants pinned at ~28us because in-flight loads/SM
//   was register-capped (~8 per warp, exposed every source iteration).
//   Fix: double-buffered register stage {weights, 8 tap uint4s}; prefetch
//   source s+1 while blending source s. 128-thr blocks, launch_bounds(128,4)
//   -> 128-reg budget, 4 blocks/SM. Split accumulators break the serial
//   FFMA2 chain. Keep v6 lane tiling (8x*4d) + zero-padded branchless taps.

namespace cvk {

constexpr int S = 8, C = 16, H = 64, W = 96, D = 64, N = H * W;
constexpr int Wp = W + 4, Hp = H + 4;          // 2-pixel zero apron each side
constexpr int NP = Hp * Wp;
constexpr int SRC_PACK_BLOCKS = (S * N * 4) / 256;   // 768
constexpr int CUR_PACK_BLOCKS = (N * 4) / 256;       // 96

typedef unsigned long long ull;

// Static device scratch (zero-initialized at module load; pads never written).
__device__ uint4  g_srcA[S * NP];   // fp16 ch0..7  per padded pixel
__device__ uint4  g_srcB[S * NP];   // fp16 ch8..15 per padded pixel
__device__ float4 g_cur[4 * N];     // fp32 cur feats, plane q = ch 4q..4q+3

// ---------------------------------------------------------------- pack pass
__global__ __launch_bounds__(256)
void pack_all(const float* __restrict__ src, const float* __restrict__ cur) {
    int bid = blockIdx.x;
    if (bid < SRC_PACK_BLOCKS) {
        int idx = bid * 256 + threadIdx.x;        // h*(S*N) + s*N + n
        int h = idx / (S * N);                    // 4-channel group 0..3
        int sn = idx - h * (S * N);
        int n_local = sn % N;
        int s = sn / N;
        int y = n_local / W, x = n_local - y * W;
        const float* p = src + (size_t)s * C * N + (size_t)(4 * h) * N + n_local;
        __half2 a = __floats2half2_rn(p[0],     p[N]);
        __half2 b = __floats2half2_rn(p[2 * N], p[3 * N]);
        uint2 v;
        v.x = *reinterpret_cast<unsigned*>(&a);
        v.y = *reinterpret_cast<unsigned*>(&b);
        int pp = (s * Hp + y + 2) * Wp + (x + 2); // padded pixel index
        uint2* plane = (h < 2) ? reinterpret_cast<uint2*>(g_srcA)
                               : reinterpret_cast<uint2*>(g_srcB);
        plane[(size_t)pp * 2 + (h & 1)] = v;
    } else {
        int idx = (bid - SRC_PACK_BLOCKS) * 256 + threadIdx.x;  // q*N + n
        int q = idx / N;
        int n = idx - q * N;
        float4 f;
        f.x = cur[(size_t)(4 * q + 0) * N + n];
        f.y = cur[(size_t)(4 * q + 1) * N + n];
        f.z = cur[(size_t)(4 * q + 2) * N + n];
        f.w = cur[(size_t)(4 * q + 3) * N + n];
        g_cur[idx] = f;
    }
}

// ------------------------------------------------------------ packed helpers
__device__ __forceinline__ ull pack_f2(float lo, float hi) {
    ull u;
    asm("mov.b64 %0, {%1, %2};" : "=l"(u) : "f"(lo), "f"(hi));
    return u;
}
__device__ __forceinline__ void unpack_f2(ull u, float& lo, float& hi) {
    asm("mov.b64 {%0, %1}, %2;" : "=f"(lo), "=f"(hi) : "l"(u));
}
__device__ __forceinline__ void fma_f32x2(ull& d, ull a, ull b) {
    asm("fma.rn.f32x2 %0, %1, %2, %3;" : "=l"(d) : "l"(a), "l"(b), "l"(d));
}

// Blend 4 taps (one 16B plane = 4 half2) with fp16 weights, dot against
// packed fp32 cur pairs, accumulating into acc (f32x2).
__device__ __forceinline__ void blend_dot(ull& acc,
                                          const uint4& t00, const uint4& t10,
                                          const uint4& t01, const uint4& t11,
                                          __half2 h00, __half2 h10,
                                          __half2 h01, __half2 h11,
                                          const ull* __restrict__ cfp) {
#pragma unroll
    for (int j = 0; j < 4; j++) {
        __half2 a = *(reinterpret_cast<const __half2*>(&t00.x) + j);
        __half2 b = *(reinterpret_cast<const __half2*>(&t10.x) + j);
        __half2 c = *(reinterpret_cast<const __half2*>(&t01.x) + j);
        __half2 e = *(reinterpret_cast<const __half2*>(&t11.x) + j);
        __half2 v = __hmul2(a, h00);
        v = __hfma2(b, h10, v);
        v = __hfma2(c, h01, v);
        v = __hfma2(e, h11, v);
        float2 f = __half22float2(v);
        fma_f32x2(acc, pack_f2(f.x, f.y), cfp[j]);
    }
}

// --------------------------------------------------------------- main kernel
// Warp lane tile: 8 x * 4 d. Block: 4 warps = 4 x-tiles -> 32 x * 4 d at one
// y. Grid (3, 64, 16) = 3072 blocks.
__global__ __launch_bounds__(128, 4)
void cost_main(const float* __restrict__ exts, const float* __restrict__ Ks,
               const float* __restrict__ invK, const float* __restrict__ mnp,
               const float* __restrict__ mxp, float* __restrict__ out) {
    __shared__ float sP[S][12];
    int t = threadIdx.y * 32 + threadIdx.x;
    if (t < S * 12) {
        int s = t / 12, rc = t - 12 * s, r = rc >> 2, c = rc & 3;
        float accm = 0.f;
#pragma unroll
        for (int k = 0; k < 4; k++)
            accm += Ks[s * 16 + r * 4 + k] * exts[s * 16 + k * 4 + c];
        sP[s][rc] = accm;
    }
    __syncthreads();

    int lane = threadIdx.x;
    int xloc = lane & 7;            // 0..7 within-warp x
    int dloc = lane >> 3;           // 0..3 within-warp depth

    int x = blockIdx.x * 32 + threadIdx.y * 8 + xloc;
    int y = blockIdx.y;
    int d = blockIdx.z * 4 + dloc;
    int n = y * W + x;

    // Log-spaced depth bin (linspace(0,1,64) ramp = d/63)
    float mnv = mnp[0], mxv = mxp[0];
    float lstep = logf(mxv / mnv) * (1.f / 63.f);
    float dep = expf(logf(mnv) + lstep * (float)d);

    // Unit-depth back-projected ray
    float pxc = (float)x + 0.5f, pyc = (float)y + 0.5f;
    float rx = invK[0] * pxc + invK[1] * pyc + invK[2];
    float ry = invK[4] * pxc + invK[5] * pyc + invK[6];
    float rz = invK[8] * pxc + invK[9] * pyc + invK[10];

    // Current-frame features as 8 packed f32x2 pairs.
    ull cfp[8];
#pragma unroll
    for (int q = 0; q < 4; q++) {
        float4 f = g_cur[q * N + n];
        cfp[2 * q + 0] = pack_f2(f.x, f.y);
        cfp[2 * q + 1] = pack_f2(f.z, f.w);
    }

    // Double-buffered pipeline stage: weights + 8 tap vectors per source.
    __half2 wgt[2][4];
    uint4 tA[2][4], tB[2][4];

    auto pre = [&](int s, int p) {
        const float* P = sP[s];
        float au = P[0] * rx + P[1] * ry + P[2]  * rz;
        float av = P[4] * rx + P[5] * ry + P[6]  * rz;
        float az = P[8] * rx + P[9] * ry + P[10] * rz;
        float pu = dep * au + P[3];
        float pv = dep * av + P[7];
        float pz = dep * az + P[11];
        float iz = 1.f / (pz + 1e-8f);
        float gx = pu * iz - 0.5f;
        float gy = pv * iz - 0.5f;
        // Clamp into the apron: fully-OOB coords read zero pixels. NaN-safe.
        gx = fminf(fmaxf(gx, -1.5f), (float)W + 0.5f);
        gy = fminf(fmaxf(gy, -1.5f), (float)H + 0.5f);
        float x0f = floorf(gx), y0f = floorf(gy);
        float wx = gx - x0f, wy = gy - y0f;
        int x0 = (int)x0f, y0 = (int)y0f;

        float zm  = (pz > 0.f) ? 1.f : 0.f;     // mask = z > 0
        float wy0 = zm * (1.f - wy);
        float wy1 = zm * wy;
        float wx0 = 1.f - wx;
        wgt[p][0] = __float2half2_rn(wx0 * wy0);
        wgt[p][1] = __float2half2_rn(wx  * wy0);
        wgt[p][2] = __float2half2_rn(wx0 * wy1);
        wgt[p][3] = __float2half2_rn(wx  * wy1);

        int pp = s * NP + (y0 + 2) * Wp + (x0 + 2);
        const uint4* A  = g_srcA + pp;
        const uint4* Bq = g_srcB + pp;
        tA[p][0] = A[0];  tA[p][1] = A[1];
        tA[p][2] = A[Wp]; tA[p][3] = A[Wp + 1];
        tB[p][0] = Bq[0];  tB[p][1] = Bq[1];
        tB[p][2] = Bq[Wp]; tB[p][3] = Bq[Wp + 1];
    };

    ull accA = 0ull, accB = 0ull;   // per-plane accumulators (split chain)

    pre(0, 0);
#pragma unroll
    for (int s = 0; s < S; s++) {
        int p = s & 1;
        if (s + 1 < S) pre(s + 1, p ^ 1);   // loads of s+1 fly over blend of s
        blend_dot(accA, tA[p][0], tA[p][1], tA[p][2], tA[p][3],
                  wgt[p][0], wgt[p][1], wgt[p][2], wgt[p][3], cfp + 0);
        blend_dot(accB, tB[p][0], tB[p][1], tB[p][2], tB[p][3],
                  wgt[p][0], wgt[p][1], wgt[p][2], wgt[p][3], cfp + 4);
    }

    float la, ha, lb, hb;
    unpack_f2(accA, la, ha);
    unpack_f2(accB, lb, hb);
    out[d * N + n] = (la + lb) + (ha + hb);  // cost_volume [D,H,W]
    out[D * N + d * N + n] = dep;            // depth_planes [D,H,W]
}

}  // namespace cvk

extern "C" void kernel_launch(void* const* d_in, const int* in_sizes, int n_in,
                              void* d_out, int out_size) {
    using namespace cvk;
    const float* cur  = (const float*)d_in[0];  // [1,16,64,96]
    const float* src  = (const float*)d_in[1];  // [1,8,16,64,96]
    const float* exts = (const float*)d_in[2];  // [1,8,4,4]
    const float* Ks   = (const float*)d_in[3];  // [1,8,4,4]
    const float* invK = (const float*)d_in[4];  // [1,4,4]
    const float* mnp  = (const float*)d_in[5];  // [1,1,1,1]
    const float* mxp  = (const float*)d_in[6];  // [1,1,1,1]
    float* out = (float*)d_out;

    pack_all<<<SRC_PACK_BLOCKS + CUR_PACK_BLOCKS, 256>>>(src, cur);

    dim3 blk(32, 4);
    dim3 grd(W / 32, H, D / 4);   // 3072 blocks
    cost_main<<<grd, blk>>>(exts, Ks, invK, mnp, mxp, out);
}

// round 12
// speedup vs baseline: 1.0011x; 1.0011x over previous
#include <cuda_runtime.h>
#include <cuda_fp16.h>

// CostVolumeManager: plane-sweep cost volume. B=1, S=8, C=16, H=64, W=96, D=64.
//
// v8: instruction-budget cut (~23%) inside the proven v6 structure.
//   - fp16 tree-dot: pre-packed fp16 cur features; per source
//     8 HMUL2 + 6 HADD2 + 2 promotes + 4 FADD replaces
//     8 FFMA2 + 16 F2F + 8 packs. fp16 chains kept <= 3 deep.
//   - 2 depths per thread (d, d+4; same x) share the 9-FFMA P.ray.
//   - keep: v6 lane tiling (8x * 4d), zero-padded fp16 source planes
//     (branchless taps, single address + immediate offsets).

namespace cvk {

constexpr int S = 8, C = 16, H = 64, W = 96, D = 64, N = H * W;
constexpr int Wp = W + 4, Hp = H + 4;          // 2-pixel zero apron each side
constexpr int NP = Hp * Wp;
constexpr int SRC_PACK_BLOCKS = (S * N * 4) / 256;   // 768
constexpr int CUR_PACK_BLOCKS = (N * 4) / 256;       // 96

// Static device scratch (zero-initialized at module load; pads never written).
__device__ uint4    g_srcA[S * NP];   // fp16 ch0..7  per padded pixel
__device__ uint4    g_srcB[S * NP];   // fp16 ch8..15 per padded pixel
__device__ unsigned g_curh[N * 8];    // fp16 cur feats: [n][8 x half2]

// ---------------------------------------------------------------- pack pass
__global__ __launch_bounds__(256)
void pack_all(const float* __restrict__ src, const float* __restrict__ cur) {
    int bid = blockIdx.x;
    if (bid < SRC_PACK_BLOCKS) {
        int idx = bid * 256 + threadIdx.x;        // h*(S*N) + s*N + n
        int h = idx / (S * N);                    // 4-channel group 0..3
        int sn = idx - h * (S * N);
        int n_local = sn % N;
        int s = sn / N;
        int y = n_local / W, x = n_local - y * W;
        const float* p = src + (size_t)s * C * N + (size_t)(4 * h) * N + n_local;
        __half2 a = __floats2half2_rn(p[0],     p[N]);
        __half2 b = __floats2half2_rn(p[2 * N], p[3 * N]);
        uint2 v;
        v.x = *reinterpret_cast<unsigned*>(&a);
        v.y = *reinterpret_cast<unsigned*>(&b);
        int pp = (s * Hp + y + 2) * Wp + (x + 2); // padded pixel index
        uint2* plane = (h < 2) ? reinterpret_cast<uint2*>(g_srcA)
                               : reinterpret_cast<uint2*>(g_srcB);
        plane[(size_t)pp * 2 + (h & 1)] = v;
    } else {
        int idx = (bid - SRC_PACK_BLOCKS) * 256 + threadIdx.x;  // q*N + n
        int q = idx / N;                          // 4-channel group 0..3
        int n = idx - q * N;
        __half2 a = __floats2half2_rn(cur[(size_t)(4 * q + 0) * N + n],
                                      cur[(size_t)(4 * q + 1) * N + n]);
        __half2 b = __floats2half2_rn(cur[(size_t)(4 * q + 2) * N + n],
                                      cur[(size_t)(4 * q + 3) * N + n]);
        g_curh[n * 8 + 2 * q + 0] = *reinterpret_cast<unsigned*>(&a);
        g_curh[n * 8 + 2 * q + 1] = *reinterpret_cast<unsigned*>(&b);
    }
}

// ---------------------------------------------------------------- fp16 dot
// Blend 4 taps of one plane with fp16 weights, multiply by fp16 cur pairs,
// tree-reduce in fp16 (chains <= 3 deep), promote once, add into fp32 accs.
__device__ __forceinline__ void blend_dot_h(float& acc0, float& acc1,
                                            const uint4& t00, const uint4& t10,
                                            const uint4& t01, const uint4& t11,
                                            __half2 h00, __half2 h10,
                                            __half2 h01, __half2 h11,
                                            const uint4& curp) {
    __half2 p[4];
#pragma unroll
    for (int j = 0; j < 4; j++) {
        __half2 a = *(reinterpret_cast<const __half2*>(&t00.x) + j);
        __half2 b = *(reinterpret_cast<const __half2*>(&t10.x) + j);
        __half2 c = *(reinterpret_cast<const __half2*>(&t01.x) + j);
        __half2 e = *(reinterpret_cast<const __half2*>(&t11.x) + j);
        __half2 v = __hmul2(a, h00);
        v = __hfma2(b, h10, v);
        v = __hfma2(c, h01, v);
        v = __hfma2(e, h11, v);
        __half2 cj = *(reinterpret_cast<const __half2*>(&curp.x) + j);
        p[j] = __hmul2(v, cj);
    }
    __half2 t0 = __hadd2(p[0], p[1]);
    __half2 t1 = __hadd2(p[2], p[3]);
    __half2 u  = __hadd2(t0, t1);          // 2 partial sums, 4 terms each
    float2 f = __half22float2(u);
    acc0 += f.x;
    acc1 += f.y;
}

// One depth through one source; pz etc. precomputed by caller.
__device__ __forceinline__ void proc_depth(float& acc0, float& acc1,
                                           float pu, float pv, float pz,
                                           int sbase,
                                           const uint4& curA, const uint4& curB) {
    float iz = 1.f / (pz + 1e-8f);
    float gx = pu * iz - 0.5f;
    float gy = pv * iz - 0.5f;
    // Clamp into the apron: fully-OOB coords read zero pixels. NaN-safe.
    gx = fminf(fmaxf(gx, -1.5f), (float)W + 0.5f);
    gy = fminf(fmaxf(gy, -1.5f), (float)H + 0.5f);
    float x0f = floorf(gx), y0f = floorf(gy);
    float wx = gx - x0f, wy = gy - y0f;
    int x0 = (int)x0f, y0 = (int)y0f;

    float zm  = (pz > 0.f) ? 1.f : 0.f;        // mask = z > 0
    float wy0 = zm * (1.f - wy);
    float wy1 = zm * wy;
    float wx0 = 1.f - wx;
    __half2 h00 = __float2half2_rn(wx0 * wy0);
    __half2 h10 = __float2half2_rn(wx  * wy0);
    __half2 h01 = __float2half2_rn(wx0 * wy1);
    __half2 h11 = __float2half2_rn(wx  * wy1);

    int pp = sbase + (y0 + 2) * Wp + (x0 + 2); // single address; imm-offset taps
    const uint4* A  = g_srcA + pp;
    const uint4* Bq = g_srcB + pp;
    uint4 a00 = A[0],  a10 = A[1],  a01 = A[Wp],  a11 = A[Wp + 1];
    uint4 b00 = Bq[0], b10 = Bq[1], b01 = Bq[Wp], b11 = Bq[Wp + 1];

    blend_dot_h(acc0, acc1, a00, a10, a01, a11, h00, h10, h01, h11, curA);
    blend_dot_h(acc0, acc1, b00, b10, b01, b11, h00, h10, h01, h11, curB);
}

// --------------------------------------------------------------- main kernel
// Warp lane tile: 8 x * 4 d; each thread handles depths d and d+4.
// Block: 4 warps = 4 x-tiles -> 32 x * 8 d at one y. Grid (3, 64, 8) = 1536.
__global__ __launch_bounds__(128)
void cost_main(const float* __restrict__ exts, const float* __restrict__ Ks,
               const float* __restrict__ invK, const float* __restrict__ mnp,
               const float* __restrict__ mxp, float* __restrict__ out) {
    __shared__ float sP[S][12];
    int t = threadIdx.y * 32 + threadIdx.x;
    if (t < S * 12) {
        int s = t / 12, rc = t - 12 * s, r = rc >> 2, c = rc & 3;
        float accm = 0.f;
#pragma unroll
        for (int k = 0; k < 4; k++)
            accm += Ks[s * 16 + r * 4 + k] * exts[s * 16 + k * 4 + c];
        sP[s][rc] = accm;
    }
    __syncthreads();

    int lane = threadIdx.x;
    int xloc = lane & 7;            // 0..7 within-warp x
    int dloc = lane >> 3;           // 0..3 within-warp depth

    int x  = blockIdx.x * 32 + threadIdx.y * 8 + xloc;
    int y  = blockIdx.y;
    int d0 = blockIdx.z * 8 + dloc;          // this thread: d0 and d0+4
    int n  = y * W + x;

    // Log-spaced depth bins (linspace(0,1,64) ramp = d/63)
    float mnv = mnp[0], mxv = mxp[0];
    float lstep = logf(mxv / mnv) * (1.f / 63.f);
    float lmn = logf(mnv);
    float dep0 = expf(lmn + lstep * (float)d0);
    float dep1 = expf(lmn + lstep * (float)(d0 + 4));

    // Unit-depth back-projected ray
    float pxc = (float)x + 0.5f, pyc = (float)y + 0.5f;
    float rx = invK[0] * pxc + invK[1] * pyc + invK[2];
    float ry = invK[4] * pxc + invK[5] * pyc + invK[6];
    float rz = invK[8] * pxc + invK[9] * pyc + invK[10];

    // Current-frame features as fp16 pairs (8 half2 = two uint4).
    uint4 curA = *reinterpret_cast<const uint4*>(g_curh + n * 8);
    uint4 curB = *reinterpret_cast<const uint4*>(g_curh + n * 8 + 4);

    float a0 = 0.f, a1 = 0.f;   // depth d0:   two fp32 partial sums
    float b0 = 0.f, b1 = 0.f;   // depth d0+4

#pragma unroll
    for (int s = 0; s < S; s++) {
        const float* P = sP[s];
        float au = P[0] * rx + P[1] * ry + P[2]  * rz;   // shared by both depths
        float av = P[4] * rx + P[5] * ry + P[6]  * rz;
        float az = P[8] * rx + P[9] * ry + P[10] * rz;
        int sbase = s * NP;
        proc_depth(a0, a1, dep0 * au + P[3], dep0 * av + P[7], dep0 * az + P[11],
                   sbase, curA, curB);
        proc_depth(b0, b1, dep1 * au + P[3], dep1 * av + P[7], dep1 * az + P[11],
                   sbase, curA, curB);
    }

    out[d0 * N + n] = a0 + a1;                    // cost_volume [D,H,W]
    out[(d0 + 4) * N + n] = b0 + b1;
    out[D * N + d0 * N + n] = dep0;               // depth_planes [D,H,W]
    out[D * N + (d0 + 4) * N + n] = dep1;
}

}  // namespace cvk

extern "C" void kernel_launch(void* const* d_in, const int* in_sizes, int n_in,
                              void* d_out, int out_size) {
    using namespace cvk;
    const float* cur  = (const float*)d_in[0];  // [1,16,64,96]
    const float* src  = (const float*)d_in[1];  // [1,8,16,64,96]
    const float* exts = (const float*)d_in[2];  // [1,8,4,4]
    const float* Ks   = (const float*)d_in[3];  // [1,8,4,4]
    const float* invK = (const float*)d_in[4];  // [1,4,4]
    const float* mnp  = (const float*)d_in[5];  // [1,1,1,1]
    const float* mxp  = (const float*)d_in[6];  // [1,1,1,1]
    float* out = (float*)d_out;

    pack_all<<<SRC_PACK_BLOCKS + CUR_PACK_BLOCKS, 256>>>(src, cur);

    dim3 blk(32, 4);
    dim3 grd(W / 32, H, D / 8);   // 1536 blocks, 2 depths per thread
    cost_main<<<grd, blk>>>(exts, Ks, invK, mnp, mxp, out);
}